// round 16
// baseline (speedup 1.0000x reference)
#include <cuda_runtime.h>
#include <cuda_fp16.h>
#include <cstdint>

#define B_    2048
#define N_    38
#define E_    4
#define DIN_  9
#define L0_   512
#define NE_   152
#define ROWS_ 77824

#define NS    4              // pipeline stages
#define BROW  136            // half2 stride of A rows (and B rows at NT=128)
#define ASTG  (16*BROW)      // half2 per A k32 stage

// ---------------- device scratch ----------------
__device__ float g_h0 [(size_t)ROWS_ * 256];
__device__ float g_hs1[(size_t)ROWS_ * 256];
__device__ float g_m1 [(size_t)ROWS_ * 1024];
__device__ float g_h1 [(size_t)ROWS_ * 256];
__device__ float g_h2 [(size_t)ROWS_ * 512];
__device__ __align__(16) __half2 g_FT [(size_t)32 * ROWS_];   // layer0 A, k-major
__device__ __align__(16) __half2 g_A1 [(size_t)128 * ROWS_];  // bnrelu0(h0) k-major
__device__ __align__(16) __half2 g_A2 [(size_t)128 * ROWS_];  // bnrelu1(h1) k-major
__device__ __align__(16) __half2 g_A3 [(size_t)256 * ROWS_];  // bnrelu2(h2) k-major
__device__ __align__(16) __half2 g_W0cT[32 * 256];
__device__ __align__(16) __half2 g_W1T [(size_t)128 * 1280];
__device__ __align__(16) __half2 g_lW0T[(size_t)128 * 512];
__device__ __align__(16) __half2 g_fWT [256 * 32];
__device__ float g_sum[3][N_], g_ssq[3][N_], g_scale[3][N_], g_shift[3][N_];

// ---------------- helpers ----------------
__device__ __forceinline__ uint32_t smem_u32(const void* p) {
    uint32_t a;
    asm("{ .reg .u64 t; cvta.to.shared.u64 t, %1; cvt.u32.u64 %0, t; }" : "=r"(a) : "l"(p));
    return a;
}
__device__ __forceinline__ void bulk_g2s(uint32_t dst, const void* src, uint32_t bytes,
                                         uint32_t mbar) {
    asm volatile(
        "cp.async.bulk.shared::cluster.global.mbarrier::complete_tx::bytes [%0], [%1], %2, [%3];"
        :: "r"(dst), "l"(src), "r"(bytes), "r"(mbar) : "memory");
}
#define MBAR_INIT(a, c) asm volatile("mbarrier.init.shared.b64 [%0], %1;" :: "r"(a), "r"((uint32_t)(c)) : "memory")
#define MBAR_EXPECT(a, b) asm volatile("mbarrier.arrive.expect_tx.shared.b64 _, [%0], %1;" :: "r"(a), "r"((uint32_t)(b)) : "memory")
#define MBAR_WAIT(a, ph) do { \
    asm volatile("{\n\t.reg .pred P1;\n\tWL_%=:\n\t" \
        "mbarrier.try_wait.parity.acquire.cta.shared::cta.b64 P1, [%0], %1, 0x989680;\n\t" \
        "@P1 bra.uni WD_%=;\n\tbra.uni WL_%=;\n\tWD_%=:\n\t}" \
        :: "r"(a), "r"((uint32_t)(ph)) : "memory"); \
} while (0)
__device__ __forceinline__ void mma16(float* c, const uint32_t* a, const uint32_t* b) {
    asm volatile(
        "mma.sync.aligned.m16n8k16.row.col.f32.f16.f16.f32 "
        "{%0,%1,%2,%3},{%4,%5,%6,%7},{%8,%9},{%0,%1,%2,%3};"
        : "+f"(c[0]), "+f"(c[1]), "+f"(c[2]), "+f"(c[3])
        : "r"(a[0]), "r"(a[1]), "r"(a[2]), "r"(a[3]), "r"(b[0]), "r"(b[1]));
}

// ---------------- zero stats + logdet ----------------
__global__ void k_zero(float* __restrict__ logdet) {
    int i = blockIdx.x * 256 + threadIdx.x;
    if (i < 3 * N_) { (&g_sum[0][0])[i] = 0.f; (&g_ssq[0][0])[i] = 0.f; }
    if (i < B_) logdet[i] = 0.f;
}

// ---------------- prep: transpose + fp16-convert all weights ----------------
__global__ void k_prep(const float* __restrict__ Ws0, const float* __restrict__ We0,
                       const float* __restrict__ be0, const float* __restrict__ Ws1,
                       const float* __restrict__ We1, const float* __restrict__ lW0,
                       const float* __restrict__ fW)
{
    int i = blockIdx.x * 256 + threadIdx.x;
    if (i < 8192) {                                     // W0cT [32 k2][256 n]
        int k2 = i >> 8, n = i & 255;
        float v[2];
#pragma unroll
        for (int h = 0; h < 2; h++) {
            int k = 2 * k2 + h;
            float t = 0.f;
            if (k < 36)      { int e = k / 9; t = We0[(n * 4 + e) * 9 + (k - e * 9)]; }
            else if (k < 45) t = Ws0[n * 9 + k - 36];
            else if (k < 49) t = be0[n * 4 + k - 45];
            v[h] = t;
        }
        g_W0cT[i] = __floats2half2_rn(v[0], v[1]);
    } else if (i < 8192 + 163840) {                     // W1T [128][1280]
        int j = i - 8192, k2 = j / 1280, n = j % 1280;
        const float* r = (n < 256) ? (Ws1 + (size_t)n * 256) : (We1 + (size_t)(n - 256) * 256);
        g_W1T[j] = __floats2half2_rn(r[2 * k2], r[2 * k2 + 1]);
    } else if (i < 8192 + 163840 + 65536) {             // lW0T [128][512]
        int j = i - 8192 - 163840, k2 = j / 512, n = j % 512;
        g_lW0T[j] = __floats2half2_rn(lW0[(size_t)n * 256 + 2 * k2], lW0[(size_t)n * 256 + 2 * k2 + 1]);
    } else if (i < 8192 + 163840 + 65536 + 8192) {      // fWT [256][32]
        int j = i - 8192 - 163840 - 65536, k2 = j / 32, n = j % 32;
        float a = 0.f, b = 0.f;
        if (n < 18) { a = fW[(size_t)n * 512 + 2 * k2]; b = fW[(size_t)n * 512 + 2 * k2 + 1]; }
        g_fWT[j] = __floats2half2_rn(a, b);
    }
}

// ---------------- layer0 features -> g_FT (k-major fp16) ----------------
__global__ __launch_bounds__(256) void k_feat(const float* __restrict__ adj,
                                              const float* __restrict__ x)
{
    __shared__ float adjS[NE_][40];
    __shared__ float xsS[N_][9];
    __shared__ float Fs[N_][64];
    const int b = blockIdx.x, tid = threadIdx.x;
    const float* adjb = adj + (size_t)b * (E_ * N_ * N_);
    for (int i = tid; i < E_ * N_ * N_; i += 256) adjS[i / N_][i % N_] = adjb[i];
    for (int i = tid; i < N_ * 9; i += 256) {
        int n = i / 9, k = i - n * 9;
        xsS[n][k] = (n & 1) ? x[(b * N_ + n) * 9 + k] : 0.f;
    }
    __syncthreads();
    for (int i = tid; i < N_ * 64; i += 256) {
        int m = i >> 6, c = i & 63;
        float v = 0.f;
        if (c < 36) {
            int e = c / 9, k = c - e * 9;
            const float* ar = adjS[e * N_ + m];
#pragma unroll
            for (int n = 0; n < N_; n++) v = fmaf(ar[n], xsS[n][k], v);
        } else if (c < 45) v = xsS[m][c - 36];
        else if (c < 49) {
            const float* ar = adjS[(c - 45) * N_ + m];
#pragma unroll
            for (int n = 0; n < N_; n++) v += ar[n];
        }
        Fs[m][c] = v;
    }
    __syncthreads();
    for (int i = tid; i < 32 * N_; i += 256) {
        int k2 = i / N_, m = i - k2 * N_;
        g_FT[(size_t)k2 * ROWS_ + b * N_ + m] = __floats2half2_rn(Fs[m][2 * k2], Fs[m][2 * k2 + 1]);
    }
}

// ---------------- BN+ReLU+fp16+transpose convert pass ----------------
template<int LAYER>
__global__ __launch_bounds__(256) void k_conv()
{
    constexpr int C = (LAYER == 2) ? 512 : 256;
    const float* __restrict__ src = (LAYER == 0) ? g_h0 : (LAYER == 1) ? g_h1 : g_h2;
    __half2* __restrict__ dst = (LAYER == 0) ? g_A1 : (LAYER == 1) ? g_A2 : g_A3;

    __shared__ float ts[64][66];
    const int tid = threadIdx.x;
    const int rb = blockIdx.x * 64;
    const int cb = blockIdx.y * 64;
    const int row = tid >> 2, ch = (tid & 3) * 16;
    {
        const int n = (rb + row) % N_;
        const float sc = g_scale[LAYER][n], sh = g_shift[LAYER][n];
        const float* sp = src + (size_t)(rb + row) * C + cb + ch;
#pragma unroll
        for (int j = 0; j < 4; j++) {
            float4 v = *(const float4*)(sp + j * 4);
            ts[row][ch + j * 4 + 0] = fmaxf(fmaf(v.x, sc, sh), 0.f);
            ts[row][ch + j * 4 + 1] = fmaxf(fmaf(v.y, sc, sh), 0.f);
            ts[row][ch + j * 4 + 2] = fmaxf(fmaf(v.z, sc, sh), 0.f);
            ts[row][ch + j * 4 + 3] = fmaxf(fmaf(v.w, sc, sh), 0.f);
        }
    }
    __syncthreads();
    const int wr = tid & 63, c2b = tid >> 6;
#pragma unroll
    for (int p = 0; p < 8; p++) {
        const int c2 = c2b + p * 4;
        float2 v = *(const float2*)&ts[wr][2 * c2];
        dst[(size_t)(cb / 2 + c2) * ROWS_ + rb + wr] = __floats2half2_rn(v.x, v.y);
    }
}

// ---------------- unified PRE fp16 MMA GEMM (cp.async.bulk pipeline) ----------------
// MODE 0: h0 = FT @ W0cT + bs0, +stats0              grid(2, 608)   K=64
// MODE 1: [hs1|m1] = A1 @ W1T + bias                 grid(10, 608)  K=256
// MODE 2: h2 = A2 @ lW0T + lb0, +stats2              grid(4, 608)   K=256
// MODE 3: f = A3 @ fWT + fb; coupling+logdet         grid(1, 608)   K=512, NT=32
template<int MODE>
__global__ __launch_bounds__(256, 2) void k_gemm(
    const float* __restrict__ bias, const float* __restrict__ bias2,
    const float* __restrict__ x, float* __restrict__ out, float* __restrict__ logdet)
{
    constexpr int K2   = (MODE == 0) ? 32 : (MODE == 3) ? 256 : 128;
    constexpr int T    = K2 / 16;
    constexpr int NT   = (MODE == 3) ? 32 : 128;
    constexpr int MT   = (NT == 128) ? 4 : 1;
    constexpr int BB   = (NT == 128) ? 136 : 40;   // B row stride (half2)
    constexpr int BSTG = 16 * BB;
    constexpr int STATL = (MODE == 0) ? 0 : (MODE == 2) ? 2 : -1;
    constexpr uint32_t TXB = 16 * 512 + 16 * (NT * 4);   // bytes per stage (A + B)

    extern __shared__ char dyn[];
    __half2* Abuf = (__half2*)dyn;                       // [NS][ASTG]
    __half2* Bbuf = (__half2*)(dyn + NS * ASTG * 4);     // [NS][BSTG]
    float*   dump = (float*)dyn;                         // mode3 epilogue alias
    __shared__ float sbuf[2][40];
    __shared__ __align__(8) uint64_t mbar[NS];

    const int tid = threadIdx.x, lane = tid & 31, wid = tid >> 5;
    const int g = lane >> 2, tig = lane & 3;
    const int cb = blockIdx.x * NT;
    const int rb = blockIdx.y * 128;
    const int WROW = (NT == 128) ? (wid & 1) * 64 : wid * 16;
    const int WCOL = (NT == 128) ? (wid >> 1) * 32 : 0;
    const uint32_t aU = smem_u32(Abuf);
    const uint32_t bU = smem_u32(Bbuf);
    const uint32_t mU = smem_u32(&mbar[0]);

    const __half2* AT;
    if      (MODE == 0) AT = g_FT;
    else if (MODE == 1) AT = g_A1;
    else if (MODE == 2) AT = g_A2;
    else                AT = g_A3;
    const __half2* BT; int ldB;
    if      (MODE == 0) { BT = g_W0cT; ldB = 256;  }
    else if (MODE == 1) { BT = g_W1T;  ldB = 1280; }
    else if (MODE == 2) { BT = g_lW0T; ldB = 512;  }
    else                { BT = g_fWT;  ldB = 32;   }

    if (tid == 0) {
#pragma unroll
        for (int s = 0; s < NS; s++) MBAR_INIT(mU + s * 8, 1);
    }
    __syncthreads();

    auto issue = [&](int s) {   // tid==0 only
        const int sb = s % NS;
        const int kr = s * 16;
        MBAR_EXPECT(mU + sb * 8, TXB);
#pragma unroll
        for (int r = 0; r < 16; r++) {
            bulk_g2s(aU + (uint32_t)(sb * ASTG + r * BROW) * 4,
                     AT + (size_t)(kr + r) * ROWS_ + rb, 512, mU + sb * 8);
            bulk_g2s(bU + (uint32_t)(sb * BSTG + r * BB) * 4,
                     BT + (size_t)(kr + r) * ldB + cb, NT * 4, mU + sb * 8);
        }
    };

    float acc[MT][4][4];
#pragma unroll
    for (int a = 0; a < MT; a++)
#pragma unroll
        for (int b2 = 0; b2 < 4; b2++)
#pragma unroll
            for (int c2 = 0; c2 < 4; c2++) acc[a][b2][c2] = 0.f;

    if (tid == 0) {
#pragma unroll
        for (int s = 0; s < NS - 1; s++) if (s < T) issue(s);
    }

    for (int t = 0; t < T; t++) {
        const int sb = t % NS;
        MBAR_WAIT(mU + sb * 8, (t / NS) & 1);
        __syncthreads();    // all warps past tile t-1's reads; safe to refill its slot
        if (tid == 0) { int s2 = t + NS - 1; if (s2 < T) issue(s2); }
        const __half2* Ap2 = Abuf + sb * ASTG;
        const __half2* Bp2 = Bbuf + sb * BSTG;
#pragma unroll
        for (int kk = 0; kk < 2; kk++) {
            uint32_t af[MT][4], bf[4][2];
#pragma unroll
            for (int mt = 0; mt < MT; mt++) {
                const int m0 = WROW + mt * 16 + g;
                af[mt][0] = *(const uint32_t*)&Ap2[(kk * 8 + tig) * BROW + m0];
                af[mt][1] = *(const uint32_t*)&Ap2[(kk * 8 + tig) * BROW + m0 + 8];
                af[mt][2] = *(const uint32_t*)&Ap2[(kk * 8 + tig + 4) * BROW + m0];
                af[mt][3] = *(const uint32_t*)&Ap2[(kk * 8 + tig + 4) * BROW + m0 + 8];
            }
#pragma unroll
            for (int nt = 0; nt < 4; nt++) {
                const int n0 = WCOL + nt * 8 + g;
                bf[nt][0] = *(const uint32_t*)&Bp2[(kk * 8 + tig) * BB + n0];
                bf[nt][1] = *(const uint32_t*)&Bp2[(kk * 8 + tig + 4) * BB + n0];
            }
#pragma unroll
            for (int mt = 0; mt < MT; mt++)
#pragma unroll
                for (int nt = 0; nt < 4; nt++)
                    mma16(acc[mt][nt], af[mt], bf[nt]);
        }
    }
    __syncthreads();

    // ---- epilogues ----
    if (MODE == 3) {
#pragma unroll
        for (int nt = 0; nt < 4; nt++) {
            const int c = nt * 8 + tig * 2;
            dump[(WROW + g) * 33 + c]         = acc[0][nt][0];
            dump[(WROW + g) * 33 + c + 1]     = acc[0][nt][1];
            dump[(WROW + g + 8) * 33 + c]     = acc[0][nt][2];
            dump[(WROW + g + 8) * 33 + c + 1] = acc[0][nt][3];
        }
        __syncthreads();
        const int row = tid >> 1, part = tid & 1;
        const int grow = rb + row;
        const int b = grow / N_, n = grow % N_;
        const int d0 = part * 5, d1 = part ? 9 : 5;
        float lds = 0.f;
        for (int d = d0; d < d1; d++) {
            float sl = dump[row * 33 + d] + bias[d];
            float tv = dump[row * 33 + 9 + d] + bias[9 + d];
            float sg = 1.f / (1.f + __expf(-sl));
            float xv = x[(size_t)grow * DIN_ + d];
            out[(size_t)grow * DIN_ + d] = (n & 1) ? xv : (xv + tv) * sg;
            lds += fminf(sl, 0.f) - log1pf(__expf(-fabsf(sl)));
        }
        atomicAdd(&logdet[b], lds);
        return;
    }

    if (STATL >= 0) {
        if (tid < 40) { sbuf[0][tid] = 0.f; sbuf[1][tid] = 0.f; }
        __syncthreads();
    }
#pragma unroll
    for (int mt = 0; mt < MT; mt++) {
        const int rloc = WROW + mt * 16 + g;
        float s0 = 0.f, q0 = 0.f, s1 = 0.f, q1 = 0.f;
#pragma unroll
        for (int nt = 0; nt < 4; nt++) {
            const int col = cb + WCOL + nt * 8 + tig * 2;
            float b0, b1;
            if (MODE == 1 && cb >= 256) { b0 = bias2[col - 256]; b1 = bias2[col - 255]; }
            else                        { b0 = bias[col];        b1 = bias[col + 1];    }
            float2 v0 = make_float2(acc[mt][nt][0] + b0, acc[mt][nt][1] + b1);
            float2 v1 = make_float2(acc[mt][nt][2] + b0, acc[mt][nt][3] + b1);
            s0 += v0.x + v0.y; q0 += v0.x * v0.x + v0.y * v0.y;
            s1 += v1.x + v1.y; q1 += v1.x * v1.x + v1.y * v1.y;
            const int row = rb + rloc;
            if (MODE == 0) {
                *(float2*)&g_h0[(size_t)row * 256 + col]       = v0;
                *(float2*)&g_h0[(size_t)(row + 8) * 256 + col] = v1;
            } else if (MODE == 1) {
                if (cb < 256) {
                    *(float2*)&g_hs1[(size_t)row * 256 + col]       = v0;
                    *(float2*)&g_hs1[(size_t)(row + 8) * 256 + col] = v1;
                } else {
                    *(float2*)&g_m1[(size_t)row * 1024 + col - 256]       = v0;
                    *(float2*)&g_m1[(size_t)(row + 8) * 1024 + col - 256] = v1;
                }
            } else {
                *(float2*)&g_h2[(size_t)row * 512 + col]       = v0;
                *(float2*)&g_h2[(size_t)(row + 8) * 512 + col] = v1;
            }
        }
        if (STATL >= 0) {
            atomicAdd(&sbuf[0][(rb + rloc) % N_], s0);
            atomicAdd(&sbuf[1][(rb + rloc) % N_], q0);
            atomicAdd(&sbuf[0][(rb + rloc + 8) % N_], s1);
            atomicAdd(&sbuf[1][(rb + rloc + 8) % N_], q1);
        }
    }
    if (STATL >= 0) {
        __syncthreads();
        if (tid < N_) {
            atomicAdd(&g_sum[STATL][tid], sbuf[0][tid]);
            atomicAdd(&g_ssq[STATL][tid], sbuf[1][tid]);
        }
    }
}

// ---------------- BN stat finalize ----------------
__global__ void k_finalize(const float* __restrict__ gg, const float* __restrict__ bb,
                           float inv_count, int layer)
{
    int t = threadIdx.x;
    if (t < N_) {
        float mu  = g_sum[layer][t] * inv_count;
        float var = g_ssq[layer][t] * inv_count - mu * mu;
        float scv = gg[t] * rsqrtf(var + 1e-5f);
        g_scale[layer][t] = scv;
        g_shift[layer][t] = bb[t] - mu * scv;
    }
}

// ---------------- layer 1 einsum (unchanged, proven) ----------------
__global__ __launch_bounds__(256) void k_einsum1(const float* __restrict__ adj)
{
    extern __shared__ float smr[];
    float (*adjT)[153] = (float(*)[153])smr;
    float (*Ms)[66]    = (float(*)[66])(smr + 40 * 153);
    const int b = blockIdx.x, cc = blockIdx.y * 64, tid = threadIdx.x;

    const float* adjb = adj + (size_t)b * (E_ * N_ * N_);
    for (int i = tid; i < E_ * N_ * N_; i += 256) {
        int e = i / (N_ * N_); int r = i % (N_ * N_);
        adjT[r / N_][e * N_ + (r % N_)] = adjb[i];
    }
    for (int i = tid; i < N_ * 64; i += 256) {
        int n = i >> 6, col = i & 63;
        float4 v = *(const float4*)&g_m1[((size_t)(b * N_ + n)) * 1024 + (size_t)(cc + col) * 4];
        Ms[n][col] = v.x; Ms[N_ + n][col] = v.y; Ms[2 * N_ + n][col] = v.z; Ms[3 * N_ + n][col] = v.w;
    }
    __syncthreads();

    const int w = tid >> 5, lane = tid & 31;
    const int c = cc + lane;
    float acc[5][2];
#pragma unroll
    for (int mi = 0; mi < 5; mi++) {
        int m = w + mi * 8;
        if (m < N_) {
            acc[mi][0] = g_hs1[((size_t)(b * N_ + m)) * 256 + c];
            acc[mi][1] = g_hs1[((size_t)(b * N_ + m)) * 256 + c + 32];
        } else acc[mi][0] = acc[mi][1] = 0.f;
    }
    for (int j = 0; j < NE_; j++) {
        float mv0 = Ms[j][lane], mv1 = Ms[j][lane + 32];
#pragma unroll
        for (int mi = 0; mi < 5; mi++) {
            float av = adjT[w + mi * 8][j];
            acc[mi][0] = fmaf(av, mv0, acc[mi][0]);
            acc[mi][1] = fmaf(av, mv1, acc[mi][1]);
        }
    }
#pragma unroll
    for (int mi = 0; mi < 5; mi++) {
        int m = w + mi * 8;
        if (m < N_) {
#pragma unroll
            for (int h = 0; h < 2; h++) {
                float v = acc[mi][h];
                g_h1[((size_t)(b * N_ + m)) * 256 + c + h * 32] = v;
                float s = v, qq = v * v;
#pragma unroll
                for (int o = 16; o; o >>= 1) {
                    s  += __shfl_xor_sync(~0u, s, o);
                    qq += __shfl_xor_sync(~0u, qq, o);
                }
                if (lane == 0) { atomicAdd(&g_sum[1][m], s); atomicAdd(&g_ssq[1][m], qq); }
            }
        }
    }
}

// ---------------- launch ----------------
extern "C" void kernel_launch(void* const* d_in, const int* in_sizes, int n_in,
                              void* d_out, int out_size)
{
    const float* adj  = (const float*)d_in[0];
    const float* x    = (const float*)d_in[1];
    const float* cWs0 = (const float*)d_in[2];
    const float* cbs0 = (const float*)d_in[3];
    const float* cWe0 = (const float*)d_in[4];
    const float* cbe0 = (const float*)d_in[5];
    const float* cg0  = (const float*)d_in[6];
    const float* cb0  = (const float*)d_in[7];
    const float* cWs1 = (const float*)d_in[8];
    const float* cbs1 = (const float*)d_in[9];
    const float* cWe1 = (const float*)d_in[10];
    const float* cbe1 = (const float*)d_in[11];
    const float* cg1  = (const float*)d_in[12];
    const float* cb1  = (const float*)d_in[13];
    const float* lW0  = (const float*)d_in[14];
    const float* lb0  = (const float*)d_in[15];
    const float* lg0  = (const float*)d_in[16];
    const float* lbb0 = (const float*)d_in[17];
    const float* fW   = (const float*)d_in[18];
    const float* fb   = (const float*)d_in[19];
    float* out    = (float*)d_out;
    float* logdet = out + (size_t)B_ * N_ * DIN_;

    const int smem128 = NS * (ASTG + 16 * 136) * 4;   // 69632
    const int smem32  = NS * (ASTG + 16 * 40) * 4;    // 45056
    cudaFuncSetAttribute(k_gemm<0>, cudaFuncAttributeMaxDynamicSharedMemorySize, smem128);
    cudaFuncSetAttribute(k_gemm<1>, cudaFuncAttributeMaxDynamicSharedMemorySize, smem128);
    cudaFuncSetAttribute(k_gemm<2>, cudaFuncAttributeMaxDynamicSharedMemorySize, smem128);
    cudaFuncSetAttribute(k_gemm<3>, cudaFuncAttributeMaxDynamicSharedMemorySize, smem32);
    cudaFuncSetAttribute(k_einsum1, cudaFuncAttributeMaxDynamicSharedMemorySize, 65536);
    const int einsum_smem = (40 * 153 + NE_ * 66) * 4;

    k_zero<<<8, 256>>>(logdet);
    k_prep<<<960, 256>>>(cWs0, cWe0, cbe0, cWs1, cWe1, lW0, fW);
    k_feat<<<B_, 256>>>(adj, x);
    k_gemm<0><<<dim3(2, 608), 256, smem128>>>(cbs0, nullptr, nullptr, nullptr, nullptr);
    k_finalize<<<1, 64>>>(cg0, cb0, 1.f / ((float)B_ * 256), 0);
    k_conv<0><<<dim3(1216, 4), 256>>>();
    k_gemm<1><<<dim3(10, 608), 256, smem128>>>(cbs1, cbe1, nullptr, nullptr, nullptr);
    k_einsum1<<<dim3(B_, 4), 256, einsum_smem>>>(adj);
    k_finalize<<<1, 64>>>(cg1, cb1, 1.f / ((float)B_ * 256), 1);
    k_conv<1><<<dim3(1216, 4), 256>>>();
    k_gemm<2><<<dim3(4, 608), 256, smem128>>>(lb0, nullptr, nullptr, nullptr, nullptr);
    k_finalize<<<1, 64>>>(lg0, lbb0, 1.f / ((float)B_ * 512), 2);
    k_conv<2><<<dim3(1216, 8), 256>>>();
    k_gemm<3><<<dim3(1, 608), 256, smem32>>>(fb, nullptr, x, out, logdet);
}

// round 17
// speedup vs baseline: 1.0683x; 1.0683x over previous
#include <cuda_runtime.h>
#include <cuda_fp16.h>
#include <cstdint>

#define B_    2048
#define N_    38
#define E_    4
#define DIN_  9
#define L0_   512
#define NE_   152
#define ROWS_ 77824

#define NS    4              // cp.async stages
#define BROW  136            // half2 stride of A rows (and B rows at NT=128)
#define ASTG  (16*BROW)      // half2 per A k32 stage

// ---------------- device scratch ----------------
__device__ float g_h0 [(size_t)ROWS_ * 256];
__device__ __align__(16) __half g_hs1h[(size_t)ROWS_ * 256];   // fp16 self term
__device__ __align__(16) __half g_m1h [(size_t)ROWS_ * 1024];  // fp16 edge messages
__device__ float g_h1 [(size_t)ROWS_ * 256];
__device__ __align__(16) __half g_h2h [(size_t)ROWS_ * 512];   // fp16 pre-BN linear out
__device__ __align__(16) __half2 g_FT [(size_t)32 * ROWS_];    // layer0 A, k-major
__device__ __align__(16) __half2 g_A1 [(size_t)128 * ROWS_];   // bnrelu0(h0) k-major
__device__ __align__(16) __half2 g_A2 [(size_t)128 * ROWS_];   // bnrelu1(h1) k-major
__device__ __align__(16) __half2 g_A3 [(size_t)256 * ROWS_];   // bnrelu2(h2) k-major
__device__ __align__(16) __half2 g_W0cT[32 * 256];
__device__ __align__(16) __half2 g_W1T [(size_t)128 * 1280];
__device__ __align__(16) __half2 g_lW0T[(size_t)128 * 512];
__device__ __align__(16) __half2 g_fWT [256 * 32];
__device__ float g_sum[3][N_], g_ssq[3][N_], g_scale[3][N_], g_shift[3][N_];

// ---------------- helpers ----------------
__device__ __forceinline__ uint32_t smem_u32(const void* p) {
    uint32_t a;
    asm("{ .reg .u64 t; cvta.to.shared.u64 t, %1; cvt.u32.u64 %0, t; }" : "=r"(a) : "l"(p));
    return a;
}
__device__ __forceinline__ void cpa16(uint32_t dst, const void* src) {
    asm volatile("cp.async.ca.shared.global [%0], [%1], 16;" :: "r"(dst), "l"(src));
}
__device__ __forceinline__ void cpa_commit() { asm volatile("cp.async.commit_group;"); }
template<int W> __device__ __forceinline__ void cpa_wait() {
    asm volatile("cp.async.wait_group %0;" :: "n"(W));
}
__device__ __forceinline__ void mma16(float* c, const uint32_t* a, const uint32_t* b) {
    asm volatile(
        "mma.sync.aligned.m16n8k16.row.col.f32.f16.f16.f32 "
        "{%0,%1,%2,%3},{%4,%5,%6,%7},{%8,%9},{%0,%1,%2,%3};"
        : "+f"(c[0]), "+f"(c[1]), "+f"(c[2]), "+f"(c[3])
        : "r"(a[0]), "r"(a[1]), "r"(a[2]), "r"(a[3]), "r"(b[0]), "r"(b[1]));
}

// ---------------- zero stats + logdet ----------------
__global__ void k_zero(float* __restrict__ logdet) {
    int i = blockIdx.x * 256 + threadIdx.x;
    if (i < 3 * N_) { (&g_sum[0][0])[i] = 0.f; (&g_ssq[0][0])[i] = 0.f; }
    if (i < B_) logdet[i] = 0.f;
}

// ---------------- prep: transpose + fp16-convert all weights ----------------
__global__ void k_prep(const float* __restrict__ Ws0, const float* __restrict__ We0,
                       const float* __restrict__ be0, const float* __restrict__ Ws1,
                       const float* __restrict__ We1, const float* __restrict__ lW0,
                       const float* __restrict__ fW)
{
    int i = blockIdx.x * 256 + threadIdx.x;
    if (i < 8192) {                                     // W0cT [32 k2][256 n]
        int k2 = i >> 8, n = i & 255;
        float v[2];
#pragma unroll
        for (int h = 0; h < 2; h++) {
            int k = 2 * k2 + h;
            float t = 0.f;
            if (k < 36)      { int e = k / 9; t = We0[(n * 4 + e) * 9 + (k - e * 9)]; }
            else if (k < 45) t = Ws0[n * 9 + k - 36];
            else if (k < 49) t = be0[n * 4 + k - 45];
            v[h] = t;
        }
        g_W0cT[i] = __floats2half2_rn(v[0], v[1]);
    } else if (i < 8192 + 163840) {                     // W1T [128][1280]
        int j = i - 8192, k2 = j / 1280, n = j % 1280;
        const float* r = (n < 256) ? (Ws1 + (size_t)n * 256) : (We1 + (size_t)(n - 256) * 256);
        g_W1T[j] = __floats2half2_rn(r[2 * k2], r[2 * k2 + 1]);
    } else if (i < 8192 + 163840 + 65536) {             // lW0T [128][512]
        int j = i - 8192 - 163840, k2 = j / 512, n = j % 512;
        g_lW0T[j] = __floats2half2_rn(lW0[(size_t)n * 256 + 2 * k2], lW0[(size_t)n * 256 + 2 * k2 + 1]);
    } else if (i < 8192 + 163840 + 65536 + 8192) {      // fWT [256][32]
        int j = i - 8192 - 163840 - 65536, k2 = j / 32, n = j % 32;
        float a = 0.f, b = 0.f;
        if (n < 18) { a = fW[(size_t)n * 512 + 2 * k2]; b = fW[(size_t)n * 512 + 2 * k2 + 1]; }
        g_fWT[j] = __floats2half2_rn(a, b);
    }
}

// ---------------- layer0 features -> g_FT (k-major fp16) ----------------
__global__ __launch_bounds__(256) void k_feat(const float* __restrict__ adj,
                                              const float* __restrict__ x)
{
    __shared__ float adjS[NE_][40];
    __shared__ float xsS[N_][9];
    __shared__ float Fs[N_][64];
    const int b = blockIdx.x, tid = threadIdx.x;
    const float* adjb = adj + (size_t)b * (E_ * N_ * N_);
    for (int i = tid; i < E_ * N_ * N_; i += 256) adjS[i / N_][i % N_] = adjb[i];
    for (int i = tid; i < N_ * 9; i += 256) {
        int n = i / 9, k = i - n * 9;
        xsS[n][k] = (n & 1) ? x[(b * N_ + n) * 9 + k] : 0.f;
    }
    __syncthreads();
    for (int i = tid; i < N_ * 64; i += 256) {
        int m = i >> 6, c = i & 63;
        float v = 0.f;
        if (c < 36) {
            int e = c / 9, k = c - e * 9;
            const float* ar = adjS[e * N_ + m];
#pragma unroll
            for (int n = 0; n < N_; n++) v = fmaf(ar[n], xsS[n][k], v);
        } else if (c < 45) v = xsS[m][c - 36];
        else if (c < 49) {
            const float* ar = adjS[(c - 45) * N_ + m];
#pragma unroll
            for (int n = 0; n < N_; n++) v += ar[n];
        }
        Fs[m][c] = v;
    }
    __syncthreads();
    for (int i = tid; i < 32 * N_; i += 256) {
        int k2 = i / N_, m = i - k2 * N_;
        g_FT[(size_t)k2 * ROWS_ + b * N_ + m] = __floats2half2_rn(Fs[m][2 * k2], Fs[m][2 * k2 + 1]);
    }
}

// ---------------- BN+ReLU+fp16+transpose convert pass ----------------
// LAYER 0: g_h0 (fp32,256)  -> g_A1    LAYER 1: g_h1 (fp32,256) -> g_A2
// LAYER 2: g_h2h (fp16,512) -> g_A3
template<int LAYER>
__global__ __launch_bounds__(256) void k_conv()
{
    constexpr int C = (LAYER == 2) ? 512 : 256;
    __half2* __restrict__ dst = (LAYER == 0) ? g_A1 : (LAYER == 1) ? g_A2 : g_A3;

    __shared__ float ts[64][66];
    const int tid = threadIdx.x;
    const int rb = blockIdx.x * 64;
    const int cb = blockIdx.y * 64;
    const int row = tid >> 2, ch = (tid & 3) * 16;
    {
        const int n = (rb + row) % N_;
        const float sc = g_scale[LAYER][n], sh = g_shift[LAYER][n];
        if (LAYER == 2) {
            const __half2* sp = (const __half2*)(g_h2h + (size_t)(rb + row) * C + cb + ch);
#pragma unroll
            for (int j = 0; j < 8; j++) {
                float2 f = __half22float2(sp[j]);
                ts[row][ch + 2 * j]     = fmaxf(fmaf(f.x, sc, sh), 0.f);
                ts[row][ch + 2 * j + 1] = fmaxf(fmaf(f.y, sc, sh), 0.f);
            }
        } else {
            const float* src = (LAYER == 0) ? g_h0 : g_h1;
            const float* sp = src + (size_t)(rb + row) * C + cb + ch;
#pragma unroll
            for (int j = 0; j < 4; j++) {
                float4 v = *(const float4*)(sp + j * 4);
                ts[row][ch + j * 4 + 0] = fmaxf(fmaf(v.x, sc, sh), 0.f);
                ts[row][ch + j * 4 + 1] = fmaxf(fmaf(v.y, sc, sh), 0.f);
                ts[row][ch + j * 4 + 2] = fmaxf(fmaf(v.z, sc, sh), 0.f);
                ts[row][ch + j * 4 + 3] = fmaxf(fmaf(v.w, sc, sh), 0.f);
            }
        }
    }
    __syncthreads();
    const int wr = tid & 63, c2b = tid >> 6;
#pragma unroll
    for (int p = 0; p < 8; p++) {
        const int c2 = c2b + p * 4;
        float2 v = *(const float2*)&ts[wr][2 * c2];
        dst[(size_t)(cb / 2 + c2) * ROWS_ + rb + wr] = __floats2half2_rn(v.x, v.y);
    }
}

// ---------------- unified PRE fp16 MMA GEMM (pure cp.async -> mma) ----------------
// MODE 0: h0 = FT @ W0cT + bs0, +stats0              grid(2, 608)   K=64
// MODE 1: [hs1|m1](fp16) = A1 @ W1T + bias           grid(10, 608)  K=256
// MODE 2: h2(fp16) = A2 @ lW0T + lb0, +stats2        grid(4, 608)   K=256
// MODE 3: f = A3 @ fWT + fb; coupling+logdet         grid(1, 608)   K=512, NT=32
template<int MODE>
__global__ __launch_bounds__(256, 2) void k_gemm(
    const float* __restrict__ bias, const float* __restrict__ bias2,
    const float* __restrict__ x, float* __restrict__ out, float* __restrict__ logdet)
{
    constexpr int K2   = (MODE == 0) ? 32 : (MODE == 3) ? 256 : 128;
    constexpr int T    = K2 / 16;
    constexpr int NT   = (MODE == 3) ? 32 : 128;
    constexpr int MT   = (NT == 128) ? 4 : 1;
    constexpr int BB   = (NT == 128) ? 136 : 40;   // B row stride (half2)
    constexpr int BSTG = 16 * BB;
    constexpr int STATL = (MODE == 0) ? 0 : (MODE == 2) ? 2 : -1;

    extern __shared__ char dyn[];
    __half2* Abuf = (__half2*)dyn;                       // [NS][ASTG]
    __half2* Bbuf = (__half2*)(dyn + NS * ASTG * 4);     // [NS][BSTG]
    float*   dump = (float*)dyn;                         // mode3 epilogue alias
    __shared__ float sbuf[2][40];

    const int tid = threadIdx.x, lane = tid & 31, wid = tid >> 5;
    const int g = lane >> 2, tig = lane & 3;
    const int cb = blockIdx.x * NT;
    const int rb = blockIdx.y * 128;
    const int WROW = (NT == 128) ? (wid & 1) * 64 : wid * 16;
    const int WCOL = (NT == 128) ? (wid >> 1) * 32 : 0;
    const uint32_t aU = smem_u32(Abuf);
    const uint32_t bU = smem_u32(Bbuf);

    const __half2* AT;
    if      (MODE == 0) AT = g_FT;
    else if (MODE == 1) AT = g_A1;
    else if (MODE == 2) AT = g_A2;
    else                AT = g_A3;
    const __half2* BT; int ldB;
    if      (MODE == 0) { BT = g_W0cT; ldB = 256;  }
    else if (MODE == 1) { BT = g_W1T;  ldB = 1280; }
    else if (MODE == 2) { BT = g_lW0T; ldB = 512;  }
    else                { BT = g_fWT;  ldB = 32;   }

    auto issue = [&](int s) {
        const int sb = s % NS;
        const int kr = s * 16;
        for (int c = tid; c < 512; c += 256) {
            int r = c >> 5, j = c & 31;
            cpa16(aU + (uint32_t)(sb * ASTG + r * BROW + j * 4) * 4,
                  AT + (size_t)(kr + r) * ROWS_ + rb + j * 4);
        }
        if (NT == 128) {
            for (int c = tid; c < 512; c += 256) {
                int r = c >> 5, j = c & 31;
                cpa16(bU + (uint32_t)(sb * BSTG + r * BB + j * 4) * 4,
                      BT + (size_t)(kr + r) * ldB + cb + j * 4);
            }
        } else {
            if (tid < 128) {
                int r = tid >> 3, j = tid & 7;
                cpa16(bU + (uint32_t)(sb * BSTG + r * BB + j * 4) * 4,
                      BT + (size_t)(kr + r) * ldB + cb + j * 4);
            }
        }
    };

    float acc[MT][4][4];
#pragma unroll
    for (int a = 0; a < MT; a++)
#pragma unroll
        for (int b2 = 0; b2 < 4; b2++)
#pragma unroll
            for (int c2 = 0; c2 < 4; c2++) acc[a][b2][c2] = 0.f;

#pragma unroll
    for (int s = 0; s < NS - 1; s++) { if (s < T) issue(s); cpa_commit(); }

    for (int t = 0; t < T; t++) {
        const int sb = t % NS;
        cpa_wait<NS - 2>();
        __syncthreads();
        { int s2 = t + NS - 1; if (s2 < T) issue(s2); cpa_commit(); }
        const __half2* Ap2 = Abuf + sb * ASTG;
        const __half2* Bp2 = Bbuf + sb * BSTG;
#pragma unroll
        for (int kk = 0; kk < 2; kk++) {
            uint32_t af[MT][4], bf[4][2];
#pragma unroll
            for (int mt = 0; mt < MT; mt++) {
                const int m0 = WROW + mt * 16 + g;
                af[mt][0] = *(const uint32_t*)&Ap2[(kk * 8 + tig) * BROW + m0];
                af[mt][1] = *(const uint32_t*)&Ap2[(kk * 8 + tig) * BROW + m0 + 8];
                af[mt][2] = *(const uint32_t*)&Ap2[(kk * 8 + tig + 4) * BROW + m0];
                af[mt][3] = *(const uint32_t*)&Ap2[(kk * 8 + tig + 4) * BROW + m0 + 8];
            }
#pragma unroll
            for (int nt = 0; nt < 4; nt++) {
                const int n0 = WCOL + nt * 8 + g;
                bf[nt][0] = *(const uint32_t*)&Bp2[(kk * 8 + tig) * BB + n0];
                bf[nt][1] = *(const uint32_t*)&Bp2[(kk * 8 + tig + 4) * BB + n0];
            }
#pragma unroll
            for (int mt = 0; mt < MT; mt++)
#pragma unroll
                for (int nt = 0; nt < 4; nt++)
                    mma16(acc[mt][nt], af[mt], bf[nt]);
        }
    }
    __syncthreads();

    // ---- epilogues ----
    if (MODE == 3) {
#pragma unroll
        for (int nt = 0; nt < 4; nt++) {
            const int c = nt * 8 + tig * 2;
            dump[(WROW + g) * 33 + c]         = acc[0][nt][0];
            dump[(WROW + g) * 33 + c + 1]     = acc[0][nt][1];
            dump[(WROW + g + 8) * 33 + c]     = acc[0][nt][2];
            dump[(WROW + g + 8) * 33 + c + 1] = acc[0][nt][3];
        }
        __syncthreads();
        const int row = tid >> 1, part = tid & 1;
        const int grow = rb + row;
        const int b = grow / N_, n = grow % N_;
        const int d0 = part * 5, d1 = part ? 9 : 5;
        float lds = 0.f;
        for (int d = d0; d < d1; d++) {
            float sl = dump[row * 33 + d] + bias[d];
            float tv = dump[row * 33 + 9 + d] + bias[9 + d];
            float sg = 1.f / (1.f + __expf(-sl));
            float xv = x[(size_t)grow * DIN_ + d];
            out[(size_t)grow * DIN_ + d] = (n & 1) ? xv : (xv + tv) * sg;
            lds += fminf(sl, 0.f) - log1pf(__expf(-fabsf(sl)));
        }
        atomicAdd(&logdet[b], lds);
        return;
    }

    if (STATL >= 0) {
        if (tid < 40) { sbuf[0][tid] = 0.f; sbuf[1][tid] = 0.f; }
        __syncthreads();
    }
#pragma unroll
    for (int mt = 0; mt < MT; mt++) {
        const int rloc = WROW + mt * 16 + g;
        float s0 = 0.f, q0 = 0.f, s1 = 0.f, q1 = 0.f;
#pragma unroll
        for (int nt = 0; nt < 4; nt++) {
            const int col = cb + WCOL + nt * 8 + tig * 2;
            float b0, b1;
            if (MODE == 1 && cb >= 256) { b0 = bias2[col - 256]; b1 = bias2[col - 255]; }
            else                        { b0 = bias[col];        b1 = bias[col + 1];    }
            float2 v0 = make_float2(acc[mt][nt][0] + b0, acc[mt][nt][1] + b1);
            float2 v1 = make_float2(acc[mt][nt][2] + b0, acc[mt][nt][3] + b1);
            s0 += v0.x + v0.y; q0 += v0.x * v0.x + v0.y * v0.y;
            s1 += v1.x + v1.y; q1 += v1.x * v1.x + v1.y * v1.y;
            const int row = rb + rloc;
            if (MODE == 0) {
                *(float2*)&g_h0[(size_t)row * 256 + col]       = v0;
                *(float2*)&g_h0[(size_t)(row + 8) * 256 + col] = v1;
            } else if (MODE == 1) {
                if (cb < 256) {
                    *(__half2*)&g_hs1h[(size_t)row * 256 + col]       = __floats2half2_rn(v0.x, v0.y);
                    *(__half2*)&g_hs1h[(size_t)(row + 8) * 256 + col] = __floats2half2_rn(v1.x, v1.y);
                } else {
                    *(__half2*)&g_m1h[(size_t)row * 1024 + col - 256]       = __floats2half2_rn(v0.x, v0.y);
                    *(__half2*)&g_m1h[(size_t)(row + 8) * 1024 + col - 256] = __floats2half2_rn(v1.x, v1.y);
                }
            } else {
                *(__half2*)&g_h2h[(size_t)row * 512 + col]       = __floats2half2_rn(v0.x, v0.y);
                *(__half2*)&g_h2h[(size_t)(row + 8) * 512 + col] = __floats2half2_rn(v1.x, v1.y);
            }
        }
        if (STATL >= 0) {
            atomicAdd(&sbuf[0][(rb + rloc) % N_], s0);
            atomicAdd(&sbuf[1][(rb + rloc) % N_], q0);
            atomicAdd(&sbuf[0][(rb + rloc + 8) % N_], s1);
            atomicAdd(&sbuf[1][(rb + rloc + 8) % N_], q1);
        }
    }
    if (STATL >= 0) {
        __syncthreads();
        if (tid < N_) {
            atomicAdd(&g_sum[STATL][tid], sbuf[0][tid]);
            atomicAdd(&g_ssq[STATL][tid], sbuf[1][tid]);
        }
    }
}

// ---------------- BN stat finalize ----------------
__global__ void k_finalize(const float* __restrict__ gg, const float* __restrict__ bb,
                           float inv_count, int layer)
{
    int t = threadIdx.x;
    if (t < N_) {
        float mu  = g_sum[layer][t] * inv_count;
        float var = g_ssq[layer][t] * inv_count - mu * mu;
        float scv = gg[t] * rsqrtf(var + 1e-5f);
        g_scale[layer][t] = scv;
        g_shift[layer][t] = bb[t] - mu * scv;
    }
}

// ---------------- layer 1 einsum: h1 = hs1 + adj-contract(m1), + stats ----------------
__global__ __launch_bounds__(256) void k_einsum1(const float* __restrict__ adj)
{
    extern __shared__ float smr[];
    float (*adjT)[153] = (float(*)[153])smr;
    float (*Ms)[66]    = (float(*)[66])(smr + 40 * 153);
    const int b = blockIdx.x, cc = blockIdx.y * 64, tid = threadIdx.x;

    const float* adjb = adj + (size_t)b * (E_ * N_ * N_);
    for (int i = tid; i < E_ * N_ * N_; i += 256) {
        int e = i / (N_ * N_); int r = i % (N_ * N_);
        adjT[r / N_][e * N_ + (r % N_)] = adjb[i];
    }
    for (int i = tid; i < N_ * 64; i += 256) {
        int n = i >> 6, col = i & 63;
        // 4 fp16 edge values (e=0..3) for channel cc+col of node n
        uint2 raw = *(const uint2*)&g_m1h[((size_t)(b * N_ + n)) * 1024 + (size_t)(cc + col) * 4];
        float2 f0 = __half22float2(*(const __half2*)&raw.x);
        float2 f1 = __half22float2(*(const __half2*)&raw.y);
        Ms[n][col]           = f0.x;
        Ms[N_ + n][col]      = f0.y;
        Ms[2 * N_ + n][col]  = f1.x;
        Ms[3 * N_ + n][col]  = f1.y;
    }
    __syncthreads();

    const int w = tid >> 5, lane = tid & 31;
    const int c = cc + lane;
    float acc[5][2];
#pragma unroll
    for (int mi = 0; mi < 5; mi++) {
        int m = w + mi * 8;
        if (m < N_) {
            acc[mi][0] = __half2float(g_hs1h[((size_t)(b * N_ + m)) * 256 + c]);
            acc[mi][1] = __half2float(g_hs1h[((size_t)(b * N_ + m)) * 256 + c + 32]);
        } else acc[mi][0] = acc[mi][1] = 0.f;
    }
    for (int j = 0; j < NE_; j++) {
        float mv0 = Ms[j][lane], mv1 = Ms[j][lane + 32];
#pragma unroll
        for (int mi = 0; mi < 5; mi++) {
            float av = adjT[w + mi * 8][j];
            acc[mi][0] = fmaf(av, mv0, acc[mi][0]);
            acc[mi][1] = fmaf(av, mv1, acc[mi][1]);
        }
    }
#pragma unroll
    for (int mi = 0; mi < 5; mi++) {
        int m = w + mi * 8;
        if (m < N_) {
#pragma unroll
            for (int h = 0; h < 2; h++) {
                float v = acc[mi][h];
                g_h1[((size_t)(b * N_ + m)) * 256 + c + h * 32] = v;
                float s = v, qq = v * v;
#pragma unroll
                for (int o = 16; o; o >>= 1) {
                    s  += __shfl_xor_sync(~0u, s, o);
                    qq += __shfl_xor_sync(~0u, qq, o);
                }
                if (lane == 0) { atomicAdd(&g_sum[1][m], s); atomicAdd(&g_ssq[1][m], qq); }
            }
        }
    }
}

// ---------------- launch ----------------
extern "C" void kernel_launch(void* const* d_in, const int* in_sizes, int n_in,
                              void* d_out, int out_size)
{
    const float* adj  = (const float*)d_in[0];
    const float* x    = (const float*)d_in[1];
    const float* cWs0 = (const float*)d_in[2];
    const float* cbs0 = (const float*)d_in[3];
    const float* cWe0 = (const float*)d_in[4];
    const float* cbe0 = (const float*)d_in[5];
    const float* cg0  = (const float*)d_in[6];
    const float* cb0  = (const float*)d_in[7];
    const float* cWs1 = (const float*)d_in[8];
    const float* cbs1 = (const float*)d_in[9];
    const float* cWe1 = (const float*)d_in[10];
    const float* cbe1 = (const float*)d_in[11];
    const float* cg1  = (const float*)d_in[12];
    const float* cb1  = (const float*)d_in[13];
    const float* lW0  = (const float*)d_in[14];
    const float* lb0  = (const float*)d_in[15];
    const float* lg0  = (const float*)d_in[16];
    const float* lbb0 = (const float*)d_in[17];
    const float* fW   = (const float*)d_in[18];
    const float* fb   = (const float*)d_in[19];
    float* out    = (float*)d_out;
    float* logdet = out + (size_t)B_ * N_ * DIN_;

    const int smem128 = NS * (ASTG + 16 * 136) * 4;   // 69632
    const int smem32  = NS * (ASTG + 16 * 40) * 4;    // 45056
    cudaFuncSetAttribute(k_gemm<0>, cudaFuncAttributeMaxDynamicSharedMemorySize, smem128);
    cudaFuncSetAttribute(k_gemm<1>, cudaFuncAttributeMaxDynamicSharedMemorySize, smem128);
    cudaFuncSetAttribute(k_gemm<2>, cudaFuncAttributeMaxDynamicSharedMemorySize, smem128);
    cudaFuncSetAttribute(k_gemm<3>, cudaFuncAttributeMaxDynamicSharedMemorySize, smem32);
    cudaFuncSetAttribute(k_einsum1, cudaFuncAttributeMaxDynamicSharedMemorySize, 65536);
    const int einsum_smem = (40 * 153 + NE_ * 66) * 4;

    k_zero<<<8, 256>>>(logdet);
    k_prep<<<960, 256>>>(cWs0, cWe0, cbe0, cWs1, cWe1, lW0, fW);
    k_feat<<<B_, 256>>>(adj, x);
    k_gemm<0><<<dim3(2, 608), 256, smem128>>>(cbs0, nullptr, nullptr, nullptr, nullptr);
    k_finalize<<<1, 64>>>(cg0, cb0, 1.f / ((float)B_ * 256), 0);
    k_conv<0><<<dim3(1216, 4), 256>>>();
    k_gemm<1><<<dim3(10, 608), 256, smem128>>>(cbs1, cbe1, nullptr, nullptr, nullptr);
    k_einsum1<<<dim3(B_, 4), 256, einsum_smem>>>(adj);
    k_finalize<<<1, 64>>>(cg1, cb1, 1.f / ((float)B_ * 256), 1);
    k_conv<1><<<dim3(1216, 4), 256>>>();
    k_gemm<2><<<dim3(4, 608), 256, smem128>>>(lb0, nullptr, nullptr, nullptr, nullptr);
    k_finalize<<<1, 64>>>(lg0, lbb0, 1.f / ((float)B_ * 512), 2);
    k_conv<2><<<dim3(1216, 8), 256>>>();
    k_gemm<3><<<dim3(1, 608), 256, smem32>>>(fb, nullptr, x, out, logdet);
}